// round 11
// baseline (speedup 1.0000x reference)
#include <cuda_runtime.h>
#include <cstdint>

#define L 16384
#define THREADS 1024
#define R 16

// Swizzle for the R=16 geometry (bijection on [0,16384)).
__device__ __forceinline__ int ph(int i) { return i ^ ((i >> 4) & 31); }

// Named barrier over an aligned 256-thread (8-warp) group.
__device__ __forceinline__ void bar256(int gid) {
    asm volatile("bar.sync %0, %1;" :: "r"(gid + 1), "r"(256) : "memory");
}

// Packed butterfly: (a, b) <- (a+b, a-b) elementwise on float2 (sm_100+ f32x2).
__device__ __forceinline__ void bfly2(float2& a, float2& b) {
    unsigned long long A = *reinterpret_cast<unsigned long long*>(&a);
    unsigned long long B = *reinterpret_cast<unsigned long long*>(&b);
    unsigned long long S, D;
    asm("add.rn.f32x2 %0, %1, %2;" : "=l"(S) : "l"(A), "l"(B));
    asm("sub.rn.f32x2 %0, %1, %2;" : "=l"(D) : "l"(A), "l"(B));
    a = *reinterpret_cast<float2*>(&S);
    b = *reinterpret_cast<float2*>(&D);
}

__device__ __forceinline__ void bf_d1(float2 w[8]) {
#pragma unroll
    for (int j = 0; j < 8; j++) {
        float a = w[j].x, b = w[j].y;
        w[j].x = a + b;
        w[j].y = a - b;
    }
}

template <int D2>
__device__ __forceinline__ void bf_pk(float2 w[8]) {
#pragma unroll
    for (int j = 0; j < 8; j++)
        if ((j & D2) == 0) bfly2(w[j], w[j + D2]);
}

// Full 4-bit in-register FWHT (element bits 0..3): d=1,2,4,8.
__device__ __forceinline__ void fwht4(float2 w[8]) {
    bf_d1(w);
    bf_pk<1>(w);
    bf_pk<2>(w);
    bf_pk<4>(w);
}

__device__ __forceinline__ uint32_t s2u(const void* p) {
    return (uint32_t)__cvta_generic_to_shared(p);
}

extern __shared__ float sh[];

// Two rows per CTA (sequential per region, R10 schedule). x rows arrive via
// TMA bulk copy into smem: removes the 8xLDG.128 register batches that were
// pinning regs at 64 and spilling ~160MB to DRAM in R9/R10.
__global__ void __launch_bounds__(THREADS, 1) ff_kernel(
    const float* __restrict__ x,
    const float* __restrict__ Bv,
    const float* __restrict__ Gv,
    const int* __restrict__ Pi,
    float* __restrict__ out)
{
    const int t = threadIdx.x;
    // Pass element maps (identical to the proven kernels):
    //  P1: i = t*16 + r                      (bits 0-3)   exch -> P2: intra-warp
    //  P2: i = q*256 + r*16 + s, t=q*16+s    (bits 4-7)   exch -> P3: 256-thr group
    //  P3: i = u*4096 + r*256 + m, t=u*256+m (bits 8-11)  exch -> P4: CTA
    //  P4: i = (r&3)*4096 + (r>>2)*1024 + t  (bit12 in-float2, bit13 packed)
    const int q = t >> 4, s = t & 15;
    const int u = t >> 8, m = t & 255;

    const int rowA = blockIdx.x * 2;
    const float* xrA = x + (size_t)rowA * L;
    const float* xrB = xrA + L;
    float* outA = out + (size_t)rowA * L;
    float* outB = outA + L;

    float* const shA = sh;
    float* const shB = sh + L;
    const uint32_t mbar = s2u(sh + 2 * L);   // 8 bytes after the two row buffers

    // ---- TMA prologue: both x rows -> smem, zero register cost ----
    if (t == 0) {
        asm volatile("mbarrier.init.shared.b64 [%0], 1;" :: "r"(mbar) : "memory");
    }
    __syncthreads();                    // mbar visible before anyone waits on it
    if (t == 0) {
        asm volatile("mbarrier.arrive.expect_tx.shared.b64 _, [%0], %1;"
                     :: "r"(mbar), "r"(2 * L * 4) : "memory");
        asm volatile("cp.async.bulk.shared::cta.global.mbarrier::complete_tx::bytes [%0], [%1], %2, [%3];"
                     :: "r"(s2u(shA)), "l"(xrA), "r"(L * 4), "r"(mbar) : "memory");
        asm volatile("cp.async.bulk.shared::cta.global.mbarrier::complete_tx::bytes [%0], [%1], %2, [%3];"
                     :: "r"(s2u(shB)), "l"(xrB), "r"(L * 4), "r"(mbar) : "memory");
    }
    {   // all threads wait for both rows (phase 0)
        asm volatile(
            "{\n\t"
            ".reg .pred P;\n\t"
            "W%=:\n\t"
            "mbarrier.try_wait.parity.shared.b64 P, [%0], 0;\n\t"
            "@!P bra W%=;\n\t"
            "}" :: "r"(mbar) : "memory");
    }

    float2 w[8];
    float* vf = reinterpret_cast<float*>(w);
    const int base = t * R;

    constexpr float SC = 1.0f / 16384.0f;

    // ---------- FWHT#1 P1 (bits 0-3), in-place in smem ----------
    // Row A: read natural (LDS.128), xB, butterfly, write swizzled.
    // In-place write targets blocks {t, t^1} (ph flips i bit4 = t bit0 only):
    // intra-warp hazard -> __syncwarp between read and write phases.
#pragma unroll
    for (int c = 0; c < 4; c++) {
        float4 xa = *reinterpret_cast<const float4*>(shA + base + c * 4);
        float4 bv = *reinterpret_cast<const float4*>(Bv + base + c * 4);
        vf[c * 4 + 0] = xa.x * bv.x; vf[c * 4 + 1] = xa.y * bv.y;
        vf[c * 4 + 2] = xa.z * bv.z; vf[c * 4 + 3] = xa.w * bv.w;
    }
    fwht4(w);
    __syncwarp();                       // everyone read row A before partner overwrites
#pragma unroll
    for (int r = 0; r < R; r++) shA[ph(base + r)] = vf[r];

    // Row B
#pragma unroll
    for (int c = 0; c < 4; c++) {
        float4 xb = *reinterpret_cast<const float4*>(shB + base + c * 4);
        float4 bv = *reinterpret_cast<const float4*>(Bv + base + c * 4);
        vf[c * 4 + 0] = xb.x * bv.x; vf[c * 4 + 1] = xb.y * bv.y;
        vf[c * 4 + 2] = xb.z * bv.z; vf[c * 4 + 3] = xb.w * bv.w;
    }
    fwht4(w);
    __syncwarp();                       // read row B before partner overwrites
#pragma unroll
    for (int r = 0; r < R; r++) shB[ph(base + r)] = vf[r];
    __syncwarp();                       // P1->P2 exchange is intra-warp (both rows)

    // ---------- P2 (bits 4-7) ----------
#pragma unroll
    for (int r = 0; r < R; r++) vf[r] = shA[ph(q * 256 + r * 16 + s)];
    fwht4(w);
#pragma unroll
    for (int r = 0; r < R; r++) shA[ph(q * 256 + r * 16 + s)] = vf[r];
#pragma unroll
    for (int r = 0; r < R; r++) vf[r] = shB[ph(q * 256 + r * 16 + s)];
    fwht4(w);
#pragma unroll
    for (int r = 0; r < R; r++) shB[ph(q * 256 + r * 16 + s)] = vf[r];
    bar256(u);                          // one barrier serves both rows

    // ---------- P3 (bits 8-11) ----------
#pragma unroll
    for (int r = 0; r < R; r++) vf[r] = shA[ph(u * 4096 + r * 256 + m)];
    fwht4(w);
#pragma unroll
    for (int r = 0; r < R; r++) shA[ph(u * 4096 + r * 256 + m)] = vf[r];
#pragma unroll
    for (int r = 0; r < R; r++) vf[r] = shB[ph(u * 4096 + r * 256 + m)];
    fwht4(w);
#pragma unroll
    for (int r = 0; r < R; r++) shB[ph(u * 4096 + r * 256 + m)] = vf[r];
    __syncthreads();

    // ---------- P4 (bits 12-13) ----------
#pragma unroll
    for (int r = 0; r < R; r++) vf[r] = shA[ph((r & 3) * 4096 + (r >> 2) * 1024 + t)];
    bf_d1(w); bf_pk<1>(w);
#pragma unroll
    for (int r = 0; r < R; r++) shA[ph((r & 3) * 4096 + (r >> 2) * 1024 + t)] = vf[r];
#pragma unroll
    for (int r = 0; r < R; r++) vf[r] = shB[ph((r & 3) * 4096 + (r >> 2) * 1024 + t)];
    bf_d1(w); bf_pk<1>(w);
#pragma unroll
    for (int r = 0; r < R; r++) shB[ph((r & 3) * 4096 + (r >> 2) * 1024 + t)] = vf[r];
    __syncthreads();

    // ---------- permutation gather + gain + FWHT#2-P1, row A ----------
#pragma unroll
    for (int c = 0; c < 4; c++) {
        int4   p = *reinterpret_cast<const int4*>(Pi + base + c * 4);
        float4 g = *reinterpret_cast<const float4*>(Gv + base + c * 4);
        vf[c * 4 + 0] = shA[ph(p.x)] * (g.x * SC);
        vf[c * 4 + 1] = shA[ph(p.y)] * (g.y * SC);
        vf[c * 4 + 2] = shA[ph(p.z)] * (g.z * SC);
        vf[c * 4 + 3] = shA[ph(p.w)] * (g.w * SC);
    }
    fwht4(w);
    __syncthreads();                    // all row-A gathers complete
#pragma unroll
    for (int r = 0; r < R; r++) shA[ph(base + r)] = vf[r];

    // ---------- gather + FWHT#2-P1, row B ----------
#pragma unroll
    for (int c = 0; c < 4; c++) {
        int4   p = *reinterpret_cast<const int4*>(Pi + base + c * 4);
        float4 g = *reinterpret_cast<const float4*>(Gv + base + c * 4);
        vf[c * 4 + 0] = shB[ph(p.x)] * (g.x * SC);
        vf[c * 4 + 1] = shB[ph(p.y)] * (g.y * SC);
        vf[c * 4 + 2] = shB[ph(p.z)] * (g.z * SC);
        vf[c * 4 + 3] = shB[ph(p.w)] * (g.w * SC);
    }
    fwht4(w);
    __syncthreads();                    // all row-B gathers complete
#pragma unroll
    for (int r = 0; r < R; r++) shB[ph(base + r)] = vf[r];
    __syncwarp();                       // intra-warp exchange into P2

    // ---------- FWHT#2 P2 ----------
#pragma unroll
    for (int r = 0; r < R; r++) vf[r] = shA[ph(q * 256 + r * 16 + s)];
    fwht4(w);
#pragma unroll
    for (int r = 0; r < R; r++) shA[ph(q * 256 + r * 16 + s)] = vf[r];
#pragma unroll
    for (int r = 0; r < R; r++) vf[r] = shB[ph(q * 256 + r * 16 + s)];
    fwht4(w);
#pragma unroll
    for (int r = 0; r < R; r++) shB[ph(q * 256 + r * 16 + s)] = vf[r];
    bar256(u);

    // ---------- FWHT#2 P3 ----------
#pragma unroll
    for (int r = 0; r < R; r++) vf[r] = shA[ph(u * 4096 + r * 256 + m)];
    fwht4(w);
#pragma unroll
    for (int r = 0; r < R; r++) shA[ph(u * 4096 + r * 256 + m)] = vf[r];
#pragma unroll
    for (int r = 0; r < R; r++) vf[r] = shB[ph(u * 4096 + r * 256 + m)];
    fwht4(w);
#pragma unroll
    for (int r = 0; r < R; r++) shB[ph(u * 4096 + r * 256 + m)] = vf[r];
    __syncthreads();

    // ---------- FWHT#2 P4 + final stores (coalesced STG.32) ----------
#pragma unroll
    for (int r = 0; r < R; r++) vf[r] = shA[ph((r & 3) * 4096 + (r >> 2) * 1024 + t)];
    bf_d1(w); bf_pk<1>(w);
#pragma unroll
    for (int r = 0; r < R; r++) outA[(r & 3) * 4096 + (r >> 2) * 1024 + t] = vf[r];
#pragma unroll
    for (int r = 0; r < R; r++) vf[r] = shB[ph((r & 3) * 4096 + (r >> 2) * 1024 + t)];
    bf_d1(w); bf_pk<1>(w);
#pragma unroll
    for (int r = 0; r < R; r++) outB[(r & 3) * 4096 + (r >> 2) * 1024 + t] = vf[r];
}

extern "C" void kernel_launch(void* const* d_in, const int* in_sizes, int n_in,
                              void* d_out, int out_size)
{
    const float* x  = (const float*)d_in[0];
    const float* B  = (const float*)d_in[1];
    const float* G  = (const float*)d_in[2];
    const int*   Pi = (const int*)d_in[3];
    float* out = (float*)d_out;

    const int rows = in_sizes[0] / L;   // 4096
    const int smem = 2 * L * (int)sizeof(float) + 16;   // 128 KB rows + mbarrier

    cudaFuncSetAttribute(ff_kernel, cudaFuncAttributeMaxDynamicSharedMemorySize, smem);

    ff_kernel<<<rows / 2, THREADS, smem>>>(x, B, G, Pi, out);
}